// round 5
// baseline (speedup 1.0000x reference)
#include <cuda_runtime.h>
#include <cstdint>
#include <math.h>

#define BB 64
#define LL 64
#define EE 256
#define MAXN 8192
#define MAXM 8192
#define HASHSZ 8192
#define NEG_INF (__int_as_float(0xff800000))

// ----------------- device-global state (no runtime allocation) -----------------
__device__ float g_feats[MAXN * EE];            // node features (fp32)
__device__ float g_norm[MAXN];                  // cached L2 norms
__device__ float g_outs[MAXM * EE];             // composed context vectors
__device__ float g_logits[(size_t)MAXM * MAXN]; // M x N logits (row stride MAXN)
__device__ int   g_rank[30720];                 // token value -> node id (or presence scratch)
__device__ int   g_tokens[MAXN];
__device__ int   g_index[BB * LL];
__device__ float g_cos[BB * LL];
__device__ int   g_hkey[HASHSZ];
__device__ int   g_hval[HASHSZ];
__device__ int   g_targets[MAXM * 3];
__device__ int   g_M;
__device__ int   g_nodeCount;
__device__ float g_rowloss[MAXM];

__device__ __forceinline__ float sigmoidf_(float x) { return 1.f / (1.f + expf(-x)); }

__device__ __forceinline__ float warp_dot(const float* a, const float* b) {
    int lane = threadIdx.x & 31;
    float s = 0.f;
#pragma unroll
    for (int k = 0; k < 8; k++) { int e = lane + 32 * k; s += a[e] * b[e]; }
#pragma unroll
    for (int o = 16; o; o >>= 1) s += __shfl_xor_sync(0xffffffffu, s, o);
    return s;
}

__device__ __forceinline__ float cos_ab(int a, int b) {
    float d = warp_dot(&g_feats[a * EE], &g_feats[b * EE]);
    return d / fmaxf(g_norm[a] * g_norm[b], 1e-8f);
}

// ----------------- setup kernels -----------------
__global__ void k_zero() {
    int i = blockIdx.x * blockDim.x + threadIdx.x;
    if (i < 30720) g_rank[i] = 0;
    if (i < HASHSZ) g_hkey[i] = -1;
    if (i == 0) { g_M = 0; }
}

__global__ void k_mark(const int* __restrict__ x) {
    int i = blockIdx.x * blockDim.x + threadIdx.x;
    if (i < BB * LL) g_rank[x[i]] = 1;
}

// presence flags live in one 30-bit mask -> tiny register footprint at 1024 thr
__global__ __launch_bounds__(1024) void k_rank(int NV) {
    __shared__ int scan[1024];
    int tid = threadIdx.x;
    const int CH2 = 30;
    int base = tid * CH2;
    unsigned mask = 0;
    for (int i = 0; i < CH2; i++) {
        int v = base + i;
        if (v < NV && g_rank[v]) mask |= (1u << i);
    }
    int cnt = __popc(mask);
    scan[tid] = cnt;
    __syncthreads();
    for (int o = 1; o < 1024; o <<= 1) {
        int add = (tid >= o) ? scan[tid - o] : 0;
        __syncthreads();
        scan[tid] += add;
        __syncthreads();
    }
    int run = scan[tid] - cnt;
    for (int i = 0; i < CH2; i++) {
        int v = base + i;
        if (v < NV) {
            if (mask & (1u << i)) { g_rank[v] = run; g_tokens[run] = v; run++; }
            else g_rank[v] = -1;
        }
    }
    if (tid == 1023) g_nodeCount = scan[1023] - 1;  // exclude pad token (max value)
}

__global__ void k_init_index(const int* __restrict__ x, int NV) {
    int i = blockIdx.x * blockDim.x + threadIdx.x;
    if (i < BB * LL) {
        int v = x[i];
        g_index[i] = (v == NV - 1) ? -1 : g_rank[v];
    }
}

__global__ void k_init_nodes(const float* __restrict__ emb) {
    int i = blockIdx.x;
    if (i >= g_nodeCount) return;
    int e = threadIdx.x;
    float v = emb[(size_t)g_tokens[i] * EE + e];
    g_feats[i * EE + e] = v;
    float s = v * v;
#pragma unroll
    for (int o = 16; o; o >>= 1) s += __shfl_xor_sync(0xffffffffu, s, o);
    __shared__ float red[8];
    if ((e & 31) == 0) red[e >> 5] = s;
    __syncthreads();
    if (e == 0) {
        float t = 0.f;
#pragma unroll
        for (int w = 0; w < 8; w++) t += red[w];
        g_norm[i] = sqrtf(t);
    }
}

__global__ void k_init_cos() {
    int gw = blockIdx.x * 8 + (threadIdx.x >> 5);
    if (gw >= BB * (LL - 1)) return;
    int r = gw / (LL - 1), j = gw % (LL - 1);
    int iR = g_index[r * LL + j + 1];
    float c;
    if (iR < 0) c = NEG_INF;
    else c = cos_ab(g_index[r * LL + j], iR);
    if ((threadIdx.x & 31) == 0) g_cos[r * LL + j] = c;
}

// ----------------- the merge tree (one block, 63 iterations) -----------------
__global__ __launch_bounds__(1024) void k_tree(const float* __restrict__ comp_l,
                                               const float* __restrict__ comp_r,
                                               const float* __restrict__ cb) {
    __shared__ int   sIdx[BB * LL];
    __shared__ float sCos[BB * LL];
    __shared__ int s_ms[BB], s_act[BB];
    __shared__ unsigned s_key[BB];
    __shared__ int s_found[BB], s_nid[BB], s_leadRow[BB];
    __shared__ int s_leadRank[BB], s_actRank[BB];
    __shared__ int s_newL[BB], s_newR[BB];
    __shared__ int s_numNew, s_numAct, s_nc, s_Mbase;
    __shared__ float s_sl[16], s_sr[16], s_cb[16];

    int tid = threadIdx.x, lane = tid & 31, wid = tid >> 5;
    if (tid < 16) {
        s_sl[tid] = sigmoidf_(comp_l[tid]);
        s_sr[tid] = sigmoidf_(comp_r[tid]);
        s_cb[tid] = cb[tid];
    }
    if (tid == 0) { s_nc = g_nodeCount; s_Mbase = 0; }
    for (int i = tid; i < BB * LL; i += 1024) { sIdx[i] = g_index[i]; sCos[i] = g_cos[i]; }
    __syncthreads();

    for (int W = LL; W >= 2; --W) {
        int Wp = W - 1;  // number of pairs; also new width after merge

        // 1. argmax per row (first-index tie-break), 2 rows per warp
        for (int r = wid; r < BB; r += 32) {
            float bv = NEG_INF; int bi = 1 << 30;
            for (int j = lane; j < Wp; j += 32) {
                float v = sCos[r * 64 + j];
                if (v > bv) { bv = v; bi = j; }
            }
#pragma unroll
            for (int o = 16; o; o >>= 1) {
                float ov = __shfl_xor_sync(0xffffffffu, bv, o);
                int   oi = __shfl_xor_sync(0xffffffffu, bi, o);
                if (ov > bv || (ov == bv && oi < bi)) { bv = ov; bi = oi; }
            }
            if (lane == 0) { s_ms[r] = bi; s_act[r] = (sIdx[r * 64 + 1] != -1) ? 1 : 0; }
        }
        __syncthreads();

        // 2. keys + BOUNDED parallel hash lookup (forward progress guaranteed)
        if (tid < BB) {
            int r = tid; int found = -1; unsigned key = 0xffffffffu;
            if (s_act[r]) {
                int ms = s_ms[r];
                int l = sIdx[r * 64 + ms], rr = sIdx[r * 64 + ms + 1];
                key = ((unsigned)l << 13) | (unsigned)rr;
                unsigned h = (key * 2654435761u) & (HASHSZ - 1);
                for (int p = 0; p < HASHSZ; p++) {
                    int k = g_hkey[h];
                    if (k == -1) break;
                    if ((unsigned)k == key) { found = g_hval[h]; break; }
                    h = (h + 1) & (HASHSZ - 1);
                }
            }
            s_key[r] = key; s_found[r] = found;
        }
        __syncthreads();

        // 3. within-iteration duplicate leaders (lowest row wins)
        if (tid < BB) {
            int r = tid; int lead = -1;
            if (s_act[r] && s_found[r] < 0) {
                lead = r;
                for (int q = 0; q < r; q++)
                    if (s_act[q] && s_found[q] < 0 && s_key[q] == s_key[r]) { lead = q; break; }
            }
            s_leadRow[r] = lead;
        }
        __syncthreads();

        // 4. deterministic scans (serial, 64 steps, trivial)
        if (tid == 0) {
            int nn = 0, na = 0;
            for (int r = 0; r < BB; r++) {
                s_leadRank[r] = nn; if (s_leadRow[r] == r) nn++;
                s_actRank[r]  = na; if (s_act[r]) na++;
            }
            s_numNew = nn; s_numAct = na;
        }
        __syncthreads();

        // 5. assign nids; leaders insert into hash (bounded probe)
        if (tid < BB) {
            int r = tid;
            if (s_act[r]) {
                int nid;
                if (s_found[r] >= 0) nid = s_found[r];
                else nid = s_nc + s_leadRank[s_leadRow[r]];
                s_nid[r] = nid;
                if (s_leadRow[r] == r) {
                    int k = s_leadRank[r];
                    s_newL[k] = sIdx[r * 64 + s_ms[r]];
                    s_newR[k] = sIdx[r * 64 + s_ms[r] + 1];
                    unsigned key = s_key[r];
                    unsigned h = (key * 2654435761u) & (HASHSZ - 1);
                    for (int p = 0; p < HASHSZ; p++) {
                        int old = atomicCAS(&g_hkey[h], -1, (int)key);
                        if (old == -1) { g_hval[h] = nid; break; }
                        h = (h + 1) & (HASHSZ - 1);
                    }
                }
            }
        }
        __syncthreads();

        // 6. compose new node features
        int K = s_numNew;
        for (int i = tid; i < K * EE; i += 1024) {
            int k = i >> 8, e = i & 255;
            int dst = s_nc + k;
            if (dst >= MAXN) continue;  // defensive
            float fl = g_feats[s_newL[k] * EE + e];
            float fr = g_feats[s_newR[k] * EE + e];
            g_feats[dst * EE + e] = fl * s_sl[e & 15] + fr * s_sr[e & 15] + s_cb[e & 15];
        }
        __syncthreads();

        // 6b. norms of new nodes (one warp each)
        for (int k = wid; k < K; k += 32) {
            int dst = s_nc + k;
            if (dst >= MAXN) continue;  // defensive
            const float* f = &g_feats[dst * EE];
            float s = 0.f;
#pragma unroll
            for (int q = 0; q < 8; q++) { float v = f[lane + 32 * q]; s += v * v; }
#pragma unroll
            for (int o = 16; o; o >>= 1) s += __shfl_xor_sync(0xffffffffu, s, o);
            if (lane == 0) g_norm[dst] = sqrtf(s);
        }

        // 7. record targets (reads only sIdx, safe concurrent with 6b)
        if (tid < BB && s_act[tid]) {
            int r = tid, ms = s_ms[r];
            int l = sIdx[r * 64 + ms], rr = sIdx[r * 64 + ms + 1];
            int ls = (ms == 0) ? -1 : sIdx[r * 64 + ms - 1];
            int rs = (ms + 2 >= W) ? -2 : sIdx[r * 64 + ms + 2];
            int base = s_Mbase + 2 * s_actRank[r];
            if (base + 1 < MAXM) {
                g_targets[base * 3 + 0] = l;  g_targets[base * 3 + 1] = ls; g_targets[base * 3 + 2] = rr;
                g_targets[base * 3 + 3] = rr; g_targets[base * 3 + 4] = l;  g_targets[base * 3 + 5] = rs;
            }
        }
        __syncthreads();

        // 8. compact index & cos (read to regs, sync, write)
        int nIdxCells = BB * Wp;
        int nCosCells = BB * (Wp - 1);
        int   civ[4]; float ccv[4];
#pragma unroll
        for (int s = 0; s < 4; s++) {
            int i = tid + s * 1024;
            if (i < nIdxCells) {
                int r = i / Wp, j = i - r * Wp;
                int v;
                if (s_act[r]) {
                    int ms = s_ms[r];
                    v = (j < ms) ? sIdx[r * 64 + j] : (j == ms ? s_nid[r] : sIdx[r * 64 + j + 1]);
                } else v = sIdx[r * 64 + j];
                civ[s] = v;
            }
            if (i < nCosCells) {
                int Wc = Wp - 1;
                int r = i / Wc, j = i - r * Wc;
                float v;
                if (s_act[r]) {
                    int ms = s_ms[r];
                    if (j < ms - 1)      v = sCos[r * 64 + j];
                    else if (j <= ms)    v = 0.f;   // recomputed in step 9
                    else                 v = sCos[r * 64 + j + 1];
                } else v = sCos[r * 64 + j];
                ccv[s] = v;
            }
        }
        __syncthreads();
#pragma unroll
        for (int s = 0; s < 4; s++) {
            int i = tid + s * 1024;
            if (i < nIdxCells) { int r = i / Wp, j = i - r * Wp; sIdx[r * 64 + j] = civ[s]; }
            if (i < nCosCells) { int Wc = Wp - 1; int r = i / Wc, j = i - r * Wc; sCos[r * 64 + j] = ccv[s]; }
        }
        __syncthreads();

        // 9. recompute the (at most) 2 affected cosines per active row
        for (int t = wid; t < 2 * BB; t += 32) {
            int r = t >> 1, slot = t & 1;
            if (!s_act[r]) continue;
            int ms = s_ms[r];
            if (slot == 0) {
                if (ms >= 1) {
                    float c = cos_ab(sIdx[r * 64 + ms - 1], sIdx[r * 64 + ms]);
                    if (lane == 0) sCos[r * 64 + ms - 1] = c;
                }
            } else {
                if (ms <= Wp - 2) {
                    int b = sIdx[r * 64 + ms + 1];
                    float c = (b == -1) ? NEG_INF : cos_ab(sIdx[r * 64 + ms], b);
                    if (lane == 0) sCos[r * 64 + ms] = c;
                }
            }
        }
        __syncthreads();

        // 10. advance counters
        if (tid == 0) { s_nc += s_numNew; s_Mbase += 2 * s_numAct; }
        __syncthreads();
    }

    if (tid == 0) { g_nodeCount = s_nc; g_M = s_Mbase; }
}

// append eos (N-2) and sos (N-1)
__global__ void k_finalize(const float* __restrict__ sos, const float* __restrict__ eos) {
    int nc = g_nodeCount;
    int e = threadIdx.x;
    if (blockIdx.x == 0) g_feats[nc * EE + e] = eos[e];
    else                 g_feats[(nc + 1) * EE + e] = sos[e];
}

__global__ void k_outs(const float* __restrict__ comp_l, const float* __restrict__ comp_r,
                       const float* __restrict__ cb) {
    int m = blockIdx.x;
    if (m >= g_M) return;
    int N = g_nodeCount + 2;
    int e = threadIdx.x;
    int t1 = g_targets[m * 3 + 1]; if (t1 < 0) t1 += N;
    int t2 = g_targets[m * 3 + 2]; if (t2 < 0) t2 += N;
    int c = e & 15;
    float sl = sigmoidf_(comp_l[c]), sr = sigmoidf_(comp_r[c]);
    g_outs[m * EE + e] = g_feats[t1 * EE + e] * sl + g_feats[t2 * EE + e] * sr + cb[c];
}

// ----------------- logits GEMM: C[m][n] = dot(outs[m], feats[n]) -----------------
// 128x128 tile per 256-thread block, 8x8 per thread, software-pipelined k-loop.
__global__ __launch_bounds__(256) void k_gemm() {
    int M = g_M, N = g_nodeCount + 2;
    int m0 = blockIdx.y * 128, n0 = blockIdx.x * 128;
    if (m0 >= M || n0 >= N) return;
    __shared__ float As[8][132];
    __shared__ float Bs[8][132];
    int tid = threadIdx.x;
    int tx = tid & 15, ty = tid >> 4;
    float acc[8][8];
#pragma unroll
    for (int i = 0; i < 8; i++)
#pragma unroll
        for (int j = 0; j < 8; j++) acc[i][j] = 0.f;

    int lr = tid >> 1;
    int lc = (tid & 1) * 4;
    bool aok = (m0 + lr) < M;
    bool bok = (n0 + lr) < N;
    const float* Aptr = g_outs  + (size_t)(m0 + lr) * EE + lc;
    const float* Bptr = g_feats + (size_t)(n0 + lr) * EE + lc;

    // prologue: load k0 = 0
    float4 av = aok ? *(const float4*)(Aptr) : make_float4(0, 0, 0, 0);
    float4 bv = bok ? *(const float4*)(Bptr) : make_float4(0, 0, 0, 0);

    for (int k0 = 0; k0 < EE; k0 += 8) {
        __syncthreads();
        As[lc + 0][lr] = av.x; As[lc + 1][lr] = av.y; As[lc + 2][lr] = av.z; As[lc + 3][lr] = av.w;
        Bs[lc + 0][lr] = bv.x; Bs[lc + 1][lr] = bv.y; Bs[lc + 2][lr] = bv.z; Bs[lc + 3][lr] = bv.w;
        __syncthreads();
        // prefetch next k-slice while computing this one
        if (k0 + 8 < EE) {
            av = aok ? *(const float4*)(Aptr + k0 + 8) : make_float4(0, 0, 0, 0);
            bv = bok ? *(const float4*)(Bptr + k0 + 8) : make_float4(0, 0, 0, 0);
        }
#pragma unroll
        for (int k = 0; k < 8; k++) {
            float a[8], b[8];
            *(float4*)(a)     = *(const float4*)&As[k][ty * 8];
            *(float4*)(a + 4) = *(const float4*)&As[k][ty * 8 + 4];
            *(float4*)(b)     = *(const float4*)&Bs[k][tx * 8];
            *(float4*)(b + 4) = *(const float4*)&Bs[k][tx * 8 + 4];
#pragma unroll
            for (int i = 0; i < 8; i++)
#pragma unroll
                for (int j = 0; j < 8; j++) acc[i][j] += a[i] * b[j];
        }
    }
#pragma unroll
    for (int i = 0; i < 8; i++) {
        int m = m0 + ty * 8 + i;
        if (m >= M) continue;
#pragma unroll
        for (int j = 0; j < 8; j++) {
            int n = n0 + tx * 8 + j;
            if (n < N) g_logits[(size_t)m * MAXN + n] = acc[i][j];
        }
    }
}

__global__ __launch_bounds__(256) void k_lse() {
    int m = blockIdx.x;
    if (m >= g_M) return;
    int N = g_nodeCount + 2;
    const float* row = &g_logits[(size_t)m * MAXN];
    int tid = threadIdx.x;
    __shared__ float sh[256];
    float mx = NEG_INF;
    for (int j = tid; j < N; j += 256) mx = fmaxf(mx, row[j]);
    sh[tid] = mx; __syncthreads();
    for (int o = 128; o; o >>= 1) { if (tid < o) sh[tid] = fmaxf(sh[tid], sh[tid + o]); __syncthreads(); }
    mx = sh[0]; __syncthreads();
    float se = 0.f;
    for (int j = tid; j < N; j += 256) se += expf(row[j] - mx);
    sh[tid] = se; __syncthreads();
    for (int o = 128; o; o >>= 1) { if (tid < o) sh[tid] += sh[tid + o]; __syncthreads(); }
    if (tid == 0) {
        int t0 = g_targets[m * 3];
        g_rowloss[m] = mx + logf(sh[0]) - row[t0];
    }
}

__global__ __launch_bounds__(1024) void k_reduce(float* __restrict__ out) {
    __shared__ float sh[1024];
    int M = g_M;
    float s = 0.f;
    for (int i = threadIdx.x; i < M; i += 1024) s += g_rowloss[i];
    sh[threadIdx.x] = s; __syncthreads();
    for (int o = 512; o; o >>= 1) { if (threadIdx.x < o) sh[threadIdx.x] += sh[threadIdx.x + o]; __syncthreads(); }
    if (threadIdx.x == 0) out[0] = sh[0] / (float)M;
}

// ----------------- launcher -----------------
extern "C" void kernel_launch(void* const* d_in, const int* in_sizes, int n_in,
                              void* d_out, int out_size) {
    const int*   x      = (const int*)  d_in[0];
    const float* emb    = (const float*)d_in[1];
    const float* comp_l = (const float*)d_in[2];
    const float* comp_r = (const float*)d_in[3];
    const float* cb     = (const float*)d_in[4];
    const float* sos    = (const float*)d_in[5];
    const float* eos    = (const float*)d_in[6];
    int NV = in_sizes[1] / EE;  // vocab size (pad token = NV-1)

    k_zero<<<121, 256>>>();
    k_mark<<<16, 256>>>(x);
    k_rank<<<1, 1024>>>(NV);
    k_init_index<<<16, 256>>>(x, NV);
    k_init_nodes<<<4096, 256>>>(emb);
    k_init_cos<<<504, 256>>>();
    k_tree<<<1, 1024>>>(comp_l, comp_r, cb);
    k_finalize<<<2, 256>>>(sos, eos);
    k_outs<<<MAXM, 256>>>(comp_l, comp_r, cb);
    k_gemm<<<dim3(64, 64), 256>>>();
    k_lse<<<MAXM, 256>>>();
    k_reduce<<<1, 1024>>>((float*)d_out);
}

// round 8
// speedup vs baseline: 1.2181x; 1.2181x over previous
#include <cuda_runtime.h>
#include <cuda_fp16.h>
#include <cstdint>
#include <math.h>

#define BB 64
#define LL 64
#define EE 256
#define MAXN 8192
#define MAXM 8192
#define HASHSZ 8192
#define NEG_INF (__int_as_float(0xff800000))

// ----------------- device-global state (no runtime allocation) -----------------
__device__ float g_feats[MAXN * EE];            // node features (fp32)
__device__ float g_norm[MAXN];                  // cached L2 norms
__device__ float g_outs[MAXM * EE];             // composed context vectors
__device__ float g_logits[(size_t)MAXM * MAXN]; // M x N logits (row stride MAXN)
__device__ __half g_Ahi[MAXM * EE];             // fp16 hi/lo split of g_outs
__device__ __half g_Alo[MAXM * EE];
__device__ __half g_Bhi[MAXN * EE];             // fp16 hi/lo split of g_feats
__device__ __half g_Blo[MAXN * EE];
__device__ int   g_rank[30720];                 // token value -> node id (or presence scratch)
__device__ int   g_tokens[MAXN];
__device__ int   g_index[BB * LL];
__device__ float g_cos[BB * LL];
__device__ int   g_hkey[HASHSZ];
__device__ int   g_hval[HASHSZ];
__device__ int   g_targets[MAXM * 3];
__device__ int   g_M;
__device__ int   g_nodeCount;
__device__ float g_rowloss[MAXM];

__device__ __forceinline__ float sigmoidf_(float x) { return 1.f / (1.f + expf(-x)); }

__device__ __forceinline__ float warp_dot(const float* a, const float* b) {
    int lane = threadIdx.x & 31;
    float s = 0.f;
#pragma unroll
    for (int k = 0; k < 8; k++) { int e = lane + 32 * k; s += a[e] * b[e]; }
#pragma unroll
    for (int o = 16; o; o >>= 1) s += __shfl_xor_sync(0xffffffffu, s, o);
    return s;
}

__device__ __forceinline__ float cos_ab(int a, int b) {
    float d = warp_dot(&g_feats[a * EE], &g_feats[b * EE]);
    return d / fmaxf(g_norm[a] * g_norm[b], 1e-8f);
}

// ----------------- setup kernels -----------------
__global__ void k_zero() {
    int i = blockIdx.x * blockDim.x + threadIdx.x;
    if (i < 30720) g_rank[i] = 0;
    if (i < HASHSZ) g_hkey[i] = -1;
    if (i == 0) { g_M = 0; }
}

__global__ void k_mark(const int* __restrict__ x) {
    int i = blockIdx.x * blockDim.x + threadIdx.x;
    if (i < BB * LL) g_rank[x[i]] = 1;
}

// presence flags live in one 30-bit mask -> tiny register footprint at 1024 thr
__global__ __launch_bounds__(1024) void k_rank(int NV) {
    __shared__ int scan[1024];
    int tid = threadIdx.x;
    const int CH2 = 30;
    int base = tid * CH2;
    unsigned mask = 0;
    for (int i = 0; i < CH2; i++) {
        int v = base + i;
        if (v < NV && g_rank[v]) mask |= (1u << i);
    }
    int cnt = __popc(mask);
    scan[tid] = cnt;
    __syncthreads();
    for (int o = 1; o < 1024; o <<= 1) {
        int add = (tid >= o) ? scan[tid - o] : 0;
        __syncthreads();
        scan[tid] += add;
        __syncthreads();
    }
    int run = scan[tid] - cnt;
    for (int i = 0; i < CH2; i++) {
        int v = base + i;
        if (v < NV) {
            if (mask & (1u << i)) { g_rank[v] = run; g_tokens[run] = v; run++; }
            else g_rank[v] = -1;
        }
    }
    if (tid == 1023) g_nodeCount = scan[1023] - 1;  // exclude pad token (max value)
}

__global__ void k_init_index(const int* __restrict__ x, int NV) {
    int i = blockIdx.x * blockDim.x + threadIdx.x;
    if (i < BB * LL) {
        int v = x[i];
        g_index[i] = (v == NV - 1) ? -1 : g_rank[v];
    }
}

__global__ void k_init_nodes(const float* __restrict__ emb) {
    int i = blockIdx.x;
    if (i >= g_nodeCount) return;
    int e = threadIdx.x;
    float v = emb[(size_t)g_tokens[i] * EE + e];
    g_feats[i * EE + e] = v;
    float s = v * v;
#pragma unroll
    for (int o = 16; o; o >>= 1) s += __shfl_xor_sync(0xffffffffu, s, o);
    __shared__ float red[8];
    if ((e & 31) == 0) red[e >> 5] = s;
    __syncthreads();
    if (e == 0) {
        float t = 0.f;
#pragma unroll
        for (int w = 0; w < 8; w++) t += red[w];
        g_norm[i] = sqrtf(t);
    }
}

__global__ void k_init_cos() {
    int gw = blockIdx.x * 8 + (threadIdx.x >> 5);
    if (gw >= BB * (LL - 1)) return;
    int r = gw / (LL - 1), j = gw % (LL - 1);
    int iR = g_index[r * LL + j + 1];
    float c;
    if (iR < 0) c = NEG_INF;
    else c = cos_ab(g_index[r * LL + j], iR);
    if ((threadIdx.x & 31) == 0) g_cos[r * LL + j] = c;
}

// ----------------- the merge tree (one block, 63 iterations) -----------------
__global__ __launch_bounds__(1024) void k_tree(const float* __restrict__ comp_l,
                                               const float* __restrict__ comp_r,
                                               const float* __restrict__ cb) {
    __shared__ int   sIdx[BB * LL];
    __shared__ float sCos[BB * LL];
    __shared__ int s_ms[BB], s_act[BB];
    __shared__ unsigned s_key[BB];
    __shared__ int s_found[BB], s_nid[BB], s_leadRow[BB];
    __shared__ int s_leadRank[BB], s_actRank[BB];
    __shared__ int s_newL[BB], s_newR[BB];
    __shared__ int s_numNew, s_numAct, s_nc, s_Mbase;
    __shared__ float s_sl[16], s_sr[16], s_cb[16];

    int tid = threadIdx.x, lane = tid & 31, wid = tid >> 5;
    if (tid < 16) {
        s_sl[tid] = sigmoidf_(comp_l[tid]);
        s_sr[tid] = sigmoidf_(comp_r[tid]);
        s_cb[tid] = cb[tid];
    }
    if (tid == 0) { s_nc = g_nodeCount; s_Mbase = 0; }
    for (int i = tid; i < BB * LL; i += 1024) { sIdx[i] = g_index[i]; sCos[i] = g_cos[i]; }
    __syncthreads();

    for (int W = LL; W >= 2; --W) {
        int Wp = W - 1;  // number of pairs; also new width after merge

        // 1. argmax per row (first-index tie-break), 2 rows per warp
        for (int r = wid; r < BB; r += 32) {
            float bv = NEG_INF; int bi = 1 << 30;
            for (int j = lane; j < Wp; j += 32) {
                float v = sCos[r * 64 + j];
                if (v > bv) { bv = v; bi = j; }
            }
#pragma unroll
            for (int o = 16; o; o >>= 1) {
                float ov = __shfl_xor_sync(0xffffffffu, bv, o);
                int   oi = __shfl_xor_sync(0xffffffffu, bi, o);
                if (ov > bv || (ov == bv && oi < bi)) { bv = ov; bi = oi; }
            }
            if (lane == 0) { s_ms[r] = bi; s_act[r] = (sIdx[r * 64 + 1] != -1) ? 1 : 0; }
        }
        __syncthreads();

        // 2. keys + BOUNDED parallel hash lookup (forward progress guaranteed)
        if (tid < BB) {
            int r = tid; int found = -1; unsigned key = 0xffffffffu;
            if (s_act[r]) {
                int ms = s_ms[r];
                int l = sIdx[r * 64 + ms], rr = sIdx[r * 64 + ms + 1];
                key = ((unsigned)l << 13) | (unsigned)rr;
                unsigned h = (key * 2654435761u) & (HASHSZ - 1);
                for (int p = 0; p < HASHSZ; p++) {
                    int k = g_hkey[h];
                    if (k == -1) break;
                    if ((unsigned)k == key) { found = g_hval[h]; break; }
                    h = (h + 1) & (HASHSZ - 1);
                }
            }
            s_key[r] = key; s_found[r] = found;
        }
        __syncthreads();

        // 3. within-iteration duplicate leaders (lowest row wins)
        if (tid < BB) {
            int r = tid; int lead = -1;
            if (s_act[r] && s_found[r] < 0) {
                lead = r;
                for (int q = 0; q < r; q++)
                    if (s_act[q] && s_found[q] < 0 && s_key[q] == s_key[r]) { lead = q; break; }
            }
            s_leadRow[r] = lead;
        }
        __syncthreads();

        // 4. deterministic scans (serial, 64 steps, trivial)
        if (tid == 0) {
            int nn = 0, na = 0;
            for (int r = 0; r < BB; r++) {
                s_leadRank[r] = nn; if (s_leadRow[r] == r) nn++;
                s_actRank[r]  = na; if (s_act[r]) na++;
            }
            s_numNew = nn; s_numAct = na;
        }
        __syncthreads();

        // 5. assign nids; leaders insert into hash (bounded probe)
        if (tid < BB) {
            int r = tid;
            if (s_act[r]) {
                int nid;
                if (s_found[r] >= 0) nid = s_found[r];
                else nid = s_nc + s_leadRank[s_leadRow[r]];
                s_nid[r] = nid;
                if (s_leadRow[r] == r) {
                    int k = s_leadRank[r];
                    s_newL[k] = sIdx[r * 64 + s_ms[r]];
                    s_newR[k] = sIdx[r * 64 + s_ms[r] + 1];
                    unsigned key = s_key[r];
                    unsigned h = (key * 2654435761u) & (HASHSZ - 1);
                    for (int p = 0; p < HASHSZ; p++) {
                        int old = atomicCAS(&g_hkey[h], -1, (int)key);
                        if (old == -1) { g_hval[h] = nid; break; }
                        h = (h + 1) & (HASHSZ - 1);
                    }
                }
            }
        }
        __syncthreads();

        // 6. compose new node features
        int K = s_numNew;
        for (int i = tid; i < K * EE; i += 1024) {
            int k = i >> 8, e = i & 255;
            int dst = s_nc + k;
            if (dst >= MAXN) continue;  // defensive
            float fl = g_feats[s_newL[k] * EE + e];
            float fr = g_feats[s_newR[k] * EE + e];
            g_feats[dst * EE + e] = fl * s_sl[e & 15] + fr * s_sr[e & 15] + s_cb[e & 15];
        }
        __syncthreads();

        // 6b. norms of new nodes (one warp each)
        for (int k = wid; k < K; k += 32) {
            int dst = s_nc + k;
            if (dst >= MAXN) continue;  // defensive
            const float* f = &g_feats[dst * EE];
            float s = 0.f;
#pragma unroll
            for (int q = 0; q < 8; q++) { float v = f[lane + 32 * q]; s += v * v; }
#pragma unroll
            for (int o = 16; o; o >>= 1) s += __shfl_xor_sync(0xffffffffu, s, o);
            if (lane == 0) g_norm[dst] = sqrtf(s);
        }

        // 7. record targets (reads only sIdx, safe concurrent with 6b)
        if (tid < BB && s_act[tid]) {
            int r = tid, ms = s_ms[r];
            int l = sIdx[r * 64 + ms], rr = sIdx[r * 64 + ms + 1];
            int ls = (ms == 0) ? -1 : sIdx[r * 64 + ms - 1];
            int rs = (ms + 2 >= W) ? -2 : sIdx[r * 64 + ms + 2];
            int base = s_Mbase + 2 * s_actRank[r];
            if (base + 1 < MAXM) {
                g_targets[base * 3 + 0] = l;  g_targets[base * 3 + 1] = ls; g_targets[base * 3 + 2] = rr;
                g_targets[base * 3 + 3] = rr; g_targets[base * 3 + 4] = l;  g_targets[base * 3 + 5] = rs;
            }
        }
        __syncthreads();

        // 8. compact index & cos (read to regs, sync, write)
        int nIdxCells = BB * Wp;
        int nCosCells = BB * (Wp - 1);
        int   civ[4]; float ccv[4];
#pragma unroll
        for (int s = 0; s < 4; s++) {
            int i = tid + s * 1024;
            if (i < nIdxCells) {
                int r = i / Wp, j = i - r * Wp;
                int v;
                if (s_act[r]) {
                    int ms = s_ms[r];
                    v = (j < ms) ? sIdx[r * 64 + j] : (j == ms ? s_nid[r] : sIdx[r * 64 + j + 1]);
                } else v = sIdx[r * 64 + j];
                civ[s] = v;
            }
            if (i < nCosCells) {
                int Wc = Wp - 1;
                int r = i / Wc, j = i - r * Wc;
                float v;
                if (s_act[r]) {
                    int ms = s_ms[r];
                    if (j < ms - 1)      v = sCos[r * 64 + j];
                    else if (j <= ms)    v = 0.f;   // recomputed in step 9
                    else                 v = sCos[r * 64 + j + 1];
                } else v = sCos[r * 64 + j];
                ccv[s] = v;
            }
        }
        __syncthreads();
#pragma unroll
        for (int s = 0; s < 4; s++) {
            int i = tid + s * 1024;
            if (i < nIdxCells) { int r = i / Wp, j = i - r * Wp; sIdx[r * 64 + j] = civ[s]; }
            if (i < nCosCells) { int Wc = Wp - 1; int r = i / Wc, j = i - r * Wc; sCos[r * 64 + j] = ccv[s]; }
        }
        __syncthreads();

        // 9. recompute the (at most) 2 affected cosines per active row
        for (int t = wid; t < 2 * BB; t += 32) {
            int r = t >> 1, slot = t & 1;
            if (!s_act[r]) continue;
            int ms = s_ms[r];
            if (slot == 0) {
                if (ms >= 1) {
                    float c = cos_ab(sIdx[r * 64 + ms - 1], sIdx[r * 64 + ms]);
                    if (lane == 0) sCos[r * 64 + ms - 1] = c;
                }
            } else {
                if (ms <= Wp - 2) {
                    int b = sIdx[r * 64 + ms + 1];
                    float c = (b == -1) ? NEG_INF : cos_ab(sIdx[r * 64 + ms], b);
                    if (lane == 0) sCos[r * 64 + ms] = c;
                }
            }
        }
        __syncthreads();

        // 10. advance counters
        if (tid == 0) { s_nc += s_numNew; s_Mbase += 2 * s_numAct; }
        __syncthreads();
    }

    if (tid == 0) { g_nodeCount = s_nc; g_M = s_Mbase; }
}

// append eos (N-2) and sos (N-1)
__global__ void k_finalize(const float* __restrict__ sos, const float* __restrict__ eos) {
    int nc = g_nodeCount;
    int e = threadIdx.x;
    if (blockIdx.x == 0) g_feats[nc * EE + e] = eos[e];
    else                 g_feats[(nc + 1) * EE + e] = sos[e];
}

__global__ void k_outs(const float* __restrict__ comp_l, const float* __restrict__ comp_r,
                       const float* __restrict__ cb) {
    int m = blockIdx.x;
    if (m >= g_M) return;
    int N = g_nodeCount + 2;
    int e = threadIdx.x;
    int t1 = g_targets[m * 3 + 1]; if (t1 < 0) t1 += N;
    int t2 = g_targets[m * 3 + 2]; if (t2 < 0) t2 += N;
    int c = e & 15;
    float sl = sigmoidf_(comp_l[c]), sr = sigmoidf_(comp_r[c]);
    g_outs[m * EE + e] = g_feats[t1 * EE + e] * sl + g_feats[t2 * EE + e] * sr + cb[c];
}

// ----------------- fp16 hi/lo conversion (arch-agnostic tensor path) -----------------
__global__ __launch_bounds__(256) void k_cvtA() {
    int i = blockIdx.x * 256 + threadIdx.x;
    float v = g_outs[i];
    __half h = __float2half_rn(v);
    g_Ahi[i] = h;
    g_Alo[i] = __float2half_rn(v - __half2float(h));
}
__global__ __launch_bounds__(256) void k_cvtB() {
    int i = blockIdx.x * 256 + threadIdx.x;
    float v = g_feats[i];
    __half h = __float2half_rn(v);
    g_Bhi[i] = h;
    g_Blo[i] = __float2half_rn(v - __half2float(h));
}

// ----------------- mma.sync GEMM (sm_80+ path; no tcgen05 needed) -----------------
__device__ __forceinline__ uint32_t smem_u32(const void* p) {
    uint32_t a;
    asm("{ .reg .u64 t; cvta.to.shared.u64 t, %1; cvt.u32.u64 %0, t; }" : "=r"(a) : "l"(p));
    return a;
}
__device__ __forceinline__ void ldsm_x4(uint32_t* r, uint32_t addr) {
    asm volatile("ldmatrix.sync.aligned.m8n8.x4.shared.b16 {%0,%1,%2,%3}, [%4];"
                 : "=r"(r[0]), "=r"(r[1]), "=r"(r[2]), "=r"(r[3]) : "r"(addr));
}
__device__ __forceinline__ void ldsm_x2(uint32_t* r, uint32_t addr) {
    asm volatile("ldmatrix.sync.aligned.m8n8.x2.shared.b16 {%0,%1}, [%2];"
                 : "=r"(r[0]), "=r"(r[1]) : "r"(addr));
}
__device__ __forceinline__ void mma16816(float* c, const uint32_t* a, const uint32_t* b) {
    asm volatile(
        "mma.sync.aligned.m16n8k16.row.col.f32.f16.f16.f32 "
        "{%0,%1,%2,%3}, {%4,%5,%6,%7}, {%8,%9}, {%0,%1,%2,%3};"
        : "+f"(c[0]), "+f"(c[1]), "+f"(c[2]), "+f"(c[3])
        : "r"(a[0]), "r"(a[1]), "r"(a[2]), "r"(a[3]), "r"(b[0]), "r"(b[1]));
}

#define SROW 40  // smem row stride in halves (128B+pad16B -> conflict-free ldmatrix)

__global__ __launch_bounds__(256) void k_gemm_mma() {
    __shared__ __half sAhi[128 * SROW], sAlo[128 * SROW];
    __shared__ __half sBhi[128 * SROW], sBlo[128 * SROW];
    int M = g_M, N = g_nodeCount + 2;
    int m0 = blockIdx.y * 128, n0 = blockIdx.x * 128;
    if (m0 >= M || n0 >= N) return;

    int tid = threadIdx.x, lane = tid & 31, warp = tid >> 5;
    int wm = warp >> 2, wn = warp & 3;  // 2 x 4 warp grid; warp tile 64m x 32n

    float c[4][4][4];
#pragma unroll
    for (int i = 0; i < 4; i++)
#pragma unroll
        for (int j = 0; j < 4; j++)
#pragma unroll
            for (int r = 0; r < 4; r++) c[i][j][r] = 0.f;

    uint32_t aBase = smem_u32(sAhi), alBase = smem_u32(sAlo);
    uint32_t bBase = smem_u32(sBhi), blBase = smem_u32(sBlo);

    // fragment smem addresses (fixed per thread, advance by k16)
    int aRow = wm * 64 + (lane & 15);
    int aCol = 8 * (lane >> 4);
    int l16 = lane & 15;
    int bCol = 8 * (l16 >> 3);

    for (int kc = 0; kc < 8; kc++) {
        __syncthreads();  // previous compute done before smem overwrite
#pragma unroll
        for (int s = 0; s < 2; s++) {
            int id = tid + s * 256;              // 0..511
            int row = id >> 2, kg = id & 3;      // row 0..127, kgrp 0..3
            size_t goff = (size_t)row * EE + kc * 32 + kg * 8;
            int soff = row * SROW + kg * 8;
            *(uint4*)&sAhi[soff] = *(const uint4*)&g_Ahi[(size_t)m0 * EE + goff];
            *(uint4*)&sAlo[soff] = *(const uint4*)&g_Alo[(size_t)m0 * EE + goff];
            *(uint4*)&sBhi[soff] = *(const uint4*)&g_Bhi[(size_t)n0 * EE + goff];
            *(uint4*)&sBlo[soff] = *(const uint4*)&g_Blo[(size_t)n0 * EE + goff];
        }
        __syncthreads();

#pragma unroll
        for (int k16 = 0; k16 < 2; k16++) {
            int kb = k16 * 16;
            uint32_t ahi[4][4], bhi[4][2], tmp[4][2], alo[4][4];
#pragma unroll
            for (int mt = 0; mt < 4; mt++)
                ldsm_x4(ahi[mt], aBase + ((aRow + mt * 16) * SROW + kb + aCol) * 2);
#pragma unroll
            for (int nt = 0; nt < 4; nt++)
                ldsm_x2(bhi[nt], bBase + ((wn * 32 + nt * 8 + (l16 & 7)) * SROW + kb + bCol) * 2);
#pragma unroll
            for (int mt = 0; mt < 4; mt++)
#pragma unroll
                for (int nt = 0; nt < 4; nt++) mma16816(c[mt][nt], ahi[mt], bhi[nt]);
            // pass 2: Ahi * Blo
#pragma unroll
            for (int nt = 0; nt < 4; nt++)
                ldsm_x2(tmp[nt], blBase + ((wn * 32 + nt * 8 + (l16 & 7)) * SROW + kb + bCol) * 2);
#pragma unroll
            for (int mt = 0; mt < 4; mt++)
#pragma unroll
                for (int nt = 0; nt < 4; nt++) mma16816(c[mt][nt], ahi[mt], tmp[nt]);
            // pass 3: Alo * Bhi
#pragma unroll
            for (int mt = 0; mt < 4; mt++)
                ldsm_x4(alo[mt], alBase + ((aRow + mt * 16) * SROW + kb + aCol) * 2);
#pragma unroll
            for (int mt = 0; mt < 4; mt++)
#pragma unroll
                for (int nt = 0; nt < 4; nt++) mma16816(c[mt][nt], alo[mt], bhi[nt]);
        }
    }

    // epilogue: c frag -> g_logits (padding rows/cols never read downstream)
#pragma unroll
    for (int mt = 0; mt < 4; mt++) {
#pragma unroll
        for (int nt = 0; nt < 4; nt++) {
            int m = m0 + wm * 64 + mt * 16 + (lane >> 2);
            int n = n0 + wn * 32 + nt * 8 + 2 * (lane & 3);
            *(float2*)&g_logits[(size_t)m * MAXN + n] = make_float2(c[mt][nt][0], c[mt][nt][1]);
            *(float2*)&g_logits[(size_t)(m + 8) * MAXN + n] = make_float2(c[mt][nt][2], c[mt][nt][3]);
        }
    }
}

__global__ __launch_bounds__(256) void k_lse() {
    int m = blockIdx.x;
    if (m >= g_M) return;
    int N = g_nodeCount + 2;
    const float* row = &g_logits[(size_t)m * MAXN];
    int tid = threadIdx.x;
    __shared__ float sh[256];
    float mx = NEG_INF;
    for (int j = tid; j < N; j += 256) mx = fmaxf(mx, row[j]);
    sh[tid] = mx; __syncthreads();
    for (int o = 128; o; o >>= 1) { if (tid < o) sh[tid] = fmaxf(sh[tid], sh[tid + o]); __syncthreads(); }
    mx = sh[0]; __syncthreads();
    float se = 0.f;
    for (int j = tid; j < N; j += 256) se += expf(row[j] - mx);
    sh[tid] = se; __syncthreads();
    for (int o = 128; o; o >>= 1) { if (tid < o) sh[tid] += sh[tid + o]; __syncthreads(); }
    if (tid == 0) {
        int t0 = g_targets[m * 3];
        g_rowloss[m] = mx + logf(sh[0]) - row[t0];
    }
}

__global__ __launch_bounds__(1024) void k_reduce(float* __restrict__ out) {
    __shared__ float sh[1024];
    int M = g_M;
    float s = 0.f;
    for (int i = threadIdx.x; i < M; i += 1024) s += g_rowloss[i];
    sh[threadIdx.x] = s; __syncthreads();
    for (int o = 512; o; o >>= 1) { if (threadIdx.x < o) sh[threadIdx.x] += sh[threadIdx.x + o]; __syncthreads(); }
    if (threadIdx.x == 0) out[0] = sh[0] / (float)M;
}

// ----------------- launcher -----------------
extern "C" void kernel_launch(void* const* d_in, const int* in_sizes, int n_in,
                              void* d_out, int out_size) {
    const int*   x      = (const int*)  d_in[0];
    const float* emb    = (const float*)d_in[1];
    const float* comp_l = (const float*)d_in[2];
    const float* comp_r = (const float*)d_in[3];
    const float* cb     = (const float*)d_in[4];
    const float* sos    = (const float*)d_in[5];
    const float* eos    = (const float*)d_in[6];
    int NV = in_sizes[1] / EE;  // vocab size (pad token = NV-1)

    k_zero<<<121, 256>>>();
    k_mark<<<16, 256>>>(x);
    k_rank<<<1, 1024>>>(NV);
    k_init_index<<<16, 256>>>(x, NV);
    k_init_nodes<<<4096, 256>>>(emb);
    k_init_cos<<<504, 256>>>();
    k_tree<<<1, 1024>>>(comp_l, comp_r, cb);
    k_finalize<<<2, 256>>>(sos, eos);
    k_outs<<<MAXM, 256>>>(comp_l, comp_r, cb);
    k_cvtA<<<MAXM, 256>>>();
    k_cvtB<<<MAXN, 256>>>();
    k_gemm_mma<<<dim3(64, 64), 256>>>();
    k_lse<<<MAXM, 256>>>();
    k_reduce<<<1, 1024>>>((float*)d_out);
}